// round 2
// baseline (speedup 1.0000x reference)
#include <cuda_runtime.h>
#include <math.h>

// ---------------------------------------------------------------------------
// DilatedSparseRnnStack: batch-parallel persistent kernel.
// Each CTA owns 8 batch rows for the entire T=256 recurrence. No inter-CTA
// sync needed (computation is fully row-independent). Dilation state lives in
// __device__ circular buffers, sliced by row so each CTA touches only its own
// region. t==0 special-casing means no slot is read before being written in
// the same launch -> replay-deterministic without any zeroing pass.
// ---------------------------------------------------------------------------

namespace {
constexpr int T_STEPS = 256;
constexpr int BATCH   = 1024;
constexpr int IN_F    = 64;
constexpr int SSZ     = 256;   // state size
constexpr int HSZ     = 128;   // hidden carried size
constexpr int OSZ     = 128;   // output carried size
constexpr int OUT_F   = 8;
constexpr int RPC     = 8;     // batch rows per CTA
constexpr int NCTA    = BATCH / RPC;   // 128
constexpr int NTHR    = 256;
constexpr int XH_W    = 448;   // max fan_in
constexpr int XH_W4   = XH_W / 4;
}

// Circular dilation buffers. Slot layout: layer offsets {0,1,4,10}, sizes {1,3,6,12}.
// Declared as float4 for 16B alignment of vectorized access.
__device__ float4 g_bufH4[22u * BATCH * HSZ / 4];
__device__ float4 g_bufC4[22u * BATCH * SSZ / 4];

__device__ __forceinline__ float sigf(float v) {
    return 1.0f / (1.0f + __expf(-v));
}

template <int K, int DIL, int LOFF, int LI>
__device__ __forceinline__ void do_layer(
    int t, int tid, int row0,
    const float4* __restrict__ xt4,      // x_t for this CTA's rows, [RPC][16] float4
    const float*  __restrict__ W,
    const float*  __restrict__ b,
    float4* __restrict__ s_xh4,          // [RPC][XH_W4]
    float4* __restrict__ s_out4)         // [RPC][OSZ/4]
{
    const int prevSlot = LOFF + (t - 1 + DIL) % DIL;
    const int curSlot  = LOFF + (t % DIL);

    // ---- sync A: previous layer's xh reads are done; s_out is ready ----
    __syncthreads();

    // ---- build xh in shared memory ----
    int offh4;  // float4 offset where prevH starts
    if (LI == 0) {
        offh4 = IN_F / 4;  // 16
        if (tid < RPC * (IN_F / 4)) {
            int r = tid >> 4, c = tid & 15;
            s_xh4[r * XH_W4 + c] = xt4[r * (IN_F / 4) + c];
        }
    } else if (LI == 2) {
        offh4 = (OSZ + IN_F) / 4;  // 48
        {
            int r = tid >> 5, c = tid & 31;              // copy prev layer out (128 f)
            s_xh4[r * XH_W4 + c] = s_out4[r * (OSZ / 4) + c];
        }
        if (tid < RPC * (IN_F / 4)) {                    // append x_t
            int r = tid >> 4, c = tid & 15;
            s_xh4[r * XH_W4 + (OSZ / 4) + c] = xt4[r * (IN_F / 4) + c];
        }
    } else {
        offh4 = OSZ / 4;  // 32
        int r = tid >> 5, c = tid & 31;
        s_xh4[r * XH_W4 + c] = s_out4[r * (OSZ / 4) + c];
    }

    // prevH / dH sections (each RPC x 128 floats = 256 float4, all threads)
    {
        int r = tid >> 5, c = tid & 31;
        float4 pv;
        if (t > 0) {
            pv = g_bufH4[((size_t)prevSlot * BATCH + row0 + r) * (HSZ / 4) + c];
        } else {
            pv = make_float4(0.f, 0.f, 0.f, 0.f);
        }
        float4 dv = (t >= DIL)
            ? g_bufH4[((size_t)curSlot * BATCH + row0 + r) * (HSZ / 4) + c]
            : pv;
        s_xh4[r * XH_W4 + offh4 + c]                 = pv;
        s_xh4[r * XH_W4 + offh4 + (HSZ / 4) + c]     = dv;
    }

    // ---- sync B: xh is fully built ----
    __syncthreads();

    // ---- GEMM: thread tid owns gate-column j = tid for all 4 gate groups ----
    const int j = tid;
    const float4* __restrict__ w0 =
        reinterpret_cast<const float4*>(W + (size_t)(0 * 256 + j) * K);
    const float4* __restrict__ w1 =
        reinterpret_cast<const float4*>(W + (size_t)(1 * 256 + j) * K);
    const float4* __restrict__ w2 =
        reinterpret_cast<const float4*>(W + (size_t)(2 * 256 + j) * K);
    const float4* __restrict__ w3 =
        reinterpret_cast<const float4*>(W + (size_t)(3 * 256 + j) * K);

    float a0[RPC], a1[RPC], a2[RPC], a3[RPC];
#pragma unroll
    for (int r = 0; r < RPC; ++r) { a0[r] = a1[r] = a2[r] = a3[r] = 0.f; }

    constexpr int K4 = K / 4;
#pragma unroll 2
    for (int kb = 0; kb < K4; ++kb) {
        float4 wa = w0[kb];
        float4 wb = w1[kb];
        float4 wc = w2[kb];
        float4 wd = w3[kb];
#pragma unroll
        for (int r = 0; r < RPC; ++r) {
            float4 xv = s_xh4[r * XH_W4 + kb];
            a0[r] = fmaf(wa.x, xv.x, a0[r]);
            a0[r] = fmaf(wa.y, xv.y, a0[r]);
            a0[r] = fmaf(wa.z, xv.z, a0[r]);
            a0[r] = fmaf(wa.w, xv.w, a0[r]);
            a1[r] = fmaf(wb.x, xv.x, a1[r]);
            a1[r] = fmaf(wb.y, xv.y, a1[r]);
            a1[r] = fmaf(wb.z, xv.z, a1[r]);
            a1[r] = fmaf(wb.w, xv.w, a1[r]);
            a2[r] = fmaf(wc.x, xv.x, a2[r]);
            a2[r] = fmaf(wc.y, xv.y, a2[r]);
            a2[r] = fmaf(wc.z, xv.z, a2[r]);
            a2[r] = fmaf(wc.w, xv.w, a2[r]);
            a3[r] = fmaf(wd.x, xv.x, a3[r]);
            a3[r] = fmaf(wd.y, xv.y, a3[r]);
            a3[r] = fmaf(wd.z, xv.z, a3[r]);
            a3[r] = fmaf(wd.w, xv.w, a3[r]);
        }
    }

    // ---- epilogue: gates -> newC, h, out ----
    const float bb0 = b[j];
    const float bb1 = b[256 + j];
    const float bb2 = b[512 + j];
    const float bb3 = b[768 + j];

    float* __restrict__ Cbase = reinterpret_cast<float*>(g_bufC4);
    float* __restrict__ Hbase = reinterpret_cast<float*>(g_bufH4);
    float*       Ccur  = Cbase + ((size_t)curSlot  * BATCH + row0) * SSZ + j;
    const float* Cprev = Cbase + ((size_t)prevSlot * BATCH + row0) * SSZ + j;
    float*       Hcur  = Hbase + ((size_t)curSlot  * BATCH + row0) * HSZ + (j - OSZ);
    float* s_outf = reinterpret_cast<float*>(s_out4);

#pragma unroll
    for (int r = 0; r < RPC; ++r) {
        float forget = sigf(a0[r] + bb0 + 1.0f);
        float cand   = tanhf(a1[r] + bb1);
        float alpha  = sigf(a2[r] + bb2);
        float og     = sigf(a3[r] + bb3);
        float newC;
        if (t == 0) {
            newC = cand;
        } else {
            float pC = Cprev[(size_t)r * SSZ];
            float wC = pC;
            if (t >= DIL) {
                float dC = Ccur[(size_t)r * SSZ];   // value from t - DIL (pre-write)
                wC = alpha * pC + (1.0f - alpha) * dC;
            }
            newC = forget * wC + (1.0f - forget) * cand;
        }
        Ccur[(size_t)r * SSZ] = newC;
        float whole = og * newC;
        if (j < OSZ) {
            s_outf[r * OSZ + j] = whole;            // feeds next layer / output proj
        } else {
            Hcur[(size_t)r * HSZ] = whole;          // h -> circular buffer
        }
    }
}

__global__ __launch_bounds__(NTHR, 1) void rnn_stack_kernel(
    const float* __restrict__ x,
    const float* __restrict__ W0, const float* __restrict__ b0,
    const float* __restrict__ W1, const float* __restrict__ b1,
    const float* __restrict__ W2, const float* __restrict__ b2,
    const float* __restrict__ W3, const float* __restrict__ b3,
    const float* __restrict__ Wout, const float* __restrict__ bout,
    float* __restrict__ out)
{
    __shared__ float4 s_xh4[RPC * XH_W4];       // 14336 B
    __shared__ float4 s_out4[RPC * (OSZ / 4)];  //  4096 B

    const int tid  = threadIdx.x;
    const int row0 = blockIdx.x * RPC;

    for (int t = 0; t < T_STEPS; ++t) {
        const float4* xt4 = reinterpret_cast<const float4*>(x) +
                            ((size_t)t * BATCH + row0) * (IN_F / 4);

        do_layer<320,  1,  0, 0>(t, tid, row0, xt4, W0, b0, s_xh4, s_out4);
        do_layer<384,  3,  1, 1>(t, tid, row0, xt4, W1, b1, s_xh4, s_out4);
        do_layer<448,  6,  4, 2>(t, tid, row0, xt4, W2, b2, s_xh4, s_out4);
        do_layer<384, 12, 10, 3>(t, tid, row0, xt4, W3, b3, s_xh4, s_out4);

        // ---- output projection: y = out3 @ Wout^T + bout ----
        __syncthreads();
        if (tid < RPC * OUT_F) {
            int r = tid >> 3, o = tid & 7;
            const float4* wo = reinterpret_cast<const float4*>(Wout + (size_t)o * OSZ);
            const float4* ov = s_out4 + r * (OSZ / 4);
            float acc = 0.f;
#pragma unroll
            for (int q = 0; q < OSZ / 4; ++q) {
                float4 a = wo[q];
                float4 v = ov[q];
                acc = fmaf(a.x, v.x, acc);
                acc = fmaf(a.y, v.y, acc);
                acc = fmaf(a.z, v.z, acc);
                acc = fmaf(a.w, v.w, acc);
            }
            out[((size_t)t * BATCH + row0 + r) * OUT_F + o] = acc + bout[o];
        }
        // top-of-layer sync (sync A of next step's layer 0) protects s_out4 reuse
    }
}

extern "C" void kernel_launch(void* const* d_in, const int* in_sizes, int n_in,
                              void* d_out, int out_size)
{
    (void)in_sizes; (void)n_in; (void)out_size;
    rnn_stack_kernel<<<NCTA, NTHR>>>(
        (const float*)d_in[0],
        (const float*)d_in[1], (const float*)d_in[2],
        (const float*)d_in[3], (const float*)d_in[4],
        (const float*)d_in[5], (const float*)d_in[6],
        (const float*)d_in[7], (const float*)d_in[8],
        (const float*)d_in[9], (const float*)d_in[10],
        (float*)d_out);
}

// round 3
// speedup vs baseline: 1.8106x; 1.8106x over previous
#include <cuda_runtime.h>
#include <math.h>

// ---------------------------------------------------------------------------
// DilatedSparseRnnStack — R3: coalesced transposed+gate-interleaved weights,
// packed f32x2 FMA (2 batch rows per 64-bit accumulator).
//
// Prep kernel (each launch, graph-capturable): WT[k][4j+g] = W[g*256+j][k].
// Main kernel: 128 CTAs x 256 threads; CTA owns 8 batch rows for all T=256
// steps. Thread j owns gate-column j (all 4 gates). Weight loads are fully
// coalesced float4 (4 gates of column j at row k). xh staged in SMEM in
// row-pair-interleaved layout so FFMA2 accumulates 2 rows at once.
// ---------------------------------------------------------------------------

namespace {
constexpr int T_STEPS = 256;
constexpr int BATCH   = 1024;
constexpr int IN_F    = 64;
constexpr int SSZ     = 256;
constexpr int HSZ     = 128;
constexpr int OSZ     = 128;
constexpr int OUT_F   = 8;
constexpr int RPC     = 8;
constexpr int NCTA    = BATCH / RPC;   // 128
constexpr int NTHR    = 256;
constexpr int KTOT    = 320 + 384 + 448 + 384;  // 1536
}

// Transposed, gate-interleaved weights: per layer, [K][1024] where the fast
// index is 4*j+g (gates of a column adjacent -> one float4 per (k, j)).
__device__ float g_WT[(size_t)KTOT * 1024];

// Circular dilation buffers. Slot offsets {0,1,4,10}, sizes {1,3,6,12}.
__device__ float4 g_bufH4[22u * BATCH * (HSZ / 4)];
__device__ float4 g_bufC4[22u * BATCH * (SSZ / 4)];

__device__ __forceinline__ float sigf(float v) {
    return 1.0f / (1.0f + __expf(-v));
}

__device__ __forceinline__ void ffma2(unsigned long long& d,
                                      unsigned long long a,
                                      unsigned long long b) {
    asm("fma.rn.f32x2 %0, %1, %2, %0;" : "+l"(d) : "l"(a), "l"(b));
}
__device__ __forceinline__ unsigned long long dup2(float w) {
    unsigned long long r;
    asm("mov.b64 %0, {%1, %1};" : "=l"(r) : "f"(w));
    return r;
}
__device__ __forceinline__ float2 u2f2(unsigned long long v) {
    float2 f;
    asm("mov.b64 {%0, %1}, %2;" : "=f"(f.x), "=f"(f.y) : "l"(v));
    return f;
}

// ---------------------------------------------------------------------------
// Prep: transpose + gate-interleave weights. Read-coalesced over W.
// ---------------------------------------------------------------------------
__global__ void prep_kernel(const float* __restrict__ W0,
                            const float* __restrict__ W1,
                            const float* __restrict__ W2,
                            const float* __restrict__ W3)
{
    const int li = blockIdx.y;
    const float* W;
    int K, off;
    if (li == 0)      { W = W0; K = 320; off = 0; }
    else if (li == 1) { W = W1; K = 384; off = 320 * 1024; }
    else if (li == 2) { W = W2; K = 448; off = 704 * 1024; }
    else              { W = W3; K = 384; off = 1152 * 1024; }

    int idx = blockIdx.x * 256 + threadIdx.x;
    if (idx < 1024 * K) {
        int row = idx / K;           // g*256 + j
        int k   = idx - row * K;
        int g = row >> 8, j = row & 255;
        g_WT[(size_t)off + (size_t)k * 1024 + 4 * j + g] = W[idx];
    }
}

// ---------------------------------------------------------------------------
// One layer step.
// ---------------------------------------------------------------------------
template <int K, int DIL, int LOFF, int LI, int WTOFF>
__device__ __forceinline__ void do_layer(
    int t, int tid, int row0,
    const float4* __restrict__ xt4,
    float4 bias,
    float* __restrict__ s_xh,    // [K][8] row-pair interleaved
    float* __restrict__ s_out)   // [128 j][8 r]
{
    const int prevSlot = LOFF + (t - 1 + DIL) % DIL;
    const int curSlot  = LOFF + (t % DIL);

    __syncthreads();  // sync A: prev layer's consumers done

    // ---- build xh in SMEM, layout s_xh[k*8 + r] ----
    // out section (layers 1..3) sits at k-offset 0 and s_out is already in
    // the same [j*8+r] layout -> straight contiguous copy.
    if (LI > 0) {
        reinterpret_cast<float4*>(s_xh)[tid] =
            reinterpret_cast<const float4*>(s_out)[tid];
    }
    // x section
    if (LI == 0 || LI == 2) {
        constexpr int XOFF = (LI == 0) ? 0 : OSZ;
        if (tid < 128) {
            int r = tid & 7, k4 = tid >> 3;           // k4 in 0..15
            float4 v = xt4[r * (IN_F / 4) + k4];
            int b = (XOFF + k4 * 4) * 8 + r;
            s_xh[b]      = v.x;
            s_xh[b + 8]  = v.y;
            s_xh[b + 16] = v.z;
            s_xh[b + 24] = v.w;
        }
    }
    // prevH / dH sections
    {
        constexpr int HOFF = (LI == 0) ? IN_F : (LI == 2) ? (OSZ + IN_F) : OSZ;
        int r = tid & 7, c = tid >> 3;                // c in 0..31
        float4 pv;
        if (t > 0) {
            pv = g_bufH4[((size_t)prevSlot * BATCH + row0 + r) * (HSZ / 4) + c];
        } else {
            pv = make_float4(0.f, 0.f, 0.f, 0.f);
        }
        float4 dv = (t >= DIL)
            ? g_bufH4[((size_t)curSlot * BATCH + row0 + r) * (HSZ / 4) + c]
            : pv;
        int b1 = (HOFF + c * 4) * 8 + r;
        s_xh[b1]      = pv.x;
        s_xh[b1 + 8]  = pv.y;
        s_xh[b1 + 16] = pv.z;
        s_xh[b1 + 24] = pv.w;
        int b2 = (HOFF + HSZ + c * 4) * 8 + r;
        s_xh[b2]      = dv.x;
        s_xh[b2 + 8]  = dv.y;
        s_xh[b2 + 16] = dv.z;
        s_xh[b2 + 24] = dv.w;
    }

    __syncthreads();  // sync B: xh complete

    // ---- GEMM: coalesced weight loads, packed f32x2 accumulation ----
    const float4* __restrict__ wt4 =
        reinterpret_cast<const float4*>(g_WT + WTOFF) + tid;

    unsigned long long acc[16];   // [g*4 + rowpair]
#pragma unroll
    for (int i = 0; i < 16; ++i) acc[i] = 0ull;

#pragma unroll 4
    for (int k = 0; k < K; ++k) {
        float4 w = wt4[k * 256];
        ulonglong2 xa = *reinterpret_cast<const ulonglong2*>(s_xh + k * 8);
        ulonglong2 xb = *reinterpret_cast<const ulonglong2*>(s_xh + k * 8 + 4);
        unsigned long long w0 = dup2(w.x);
        unsigned long long w1 = dup2(w.y);
        unsigned long long w2 = dup2(w.z);
        unsigned long long w3 = dup2(w.w);
        ffma2(acc[0],  w0, xa.x); ffma2(acc[1],  w0, xa.y);
        ffma2(acc[2],  w0, xb.x); ffma2(acc[3],  w0, xb.y);
        ffma2(acc[4],  w1, xa.x); ffma2(acc[5],  w1, xa.y);
        ffma2(acc[6],  w1, xb.x); ffma2(acc[7],  w1, xb.y);
        ffma2(acc[8],  w2, xa.x); ffma2(acc[9],  w2, xa.y);
        ffma2(acc[10], w2, xb.x); ffma2(acc[11], w2, xb.y);
        ffma2(acc[12], w3, xa.x); ffma2(acc[13], w3, xa.y);
        ffma2(acc[14], w3, xb.x); ffma2(acc[15], w3, xb.y);
    }

    // ---- epilogue ----
    const int j = tid;
    float* Cbase = reinterpret_cast<float*>(g_bufC4);
    float* Hbase = reinterpret_cast<float*>(g_bufH4);
    float*       Ccur  = Cbase + ((size_t)curSlot  * BATCH + row0) * SSZ + j;
    const float* Cprev = Cbase + ((size_t)prevSlot * BATCH + row0) * SSZ + j;
    float*       Hcur  = Hbase + ((size_t)curSlot  * BATCH + row0) * HSZ + (j - OSZ);

#pragma unroll
    for (int p = 0; p < 4; ++p) {
        float2 G0 = u2f2(acc[p]);
        float2 G1 = u2f2(acc[4 + p]);
        float2 G2 = u2f2(acc[8 + p]);
        float2 G3 = u2f2(acc[12 + p]);
        float outv[2];
#pragma unroll
        for (int s = 0; s < 2; ++s) {
            int r = 2 * p + s;
            float forget = sigf((s ? G0.y : G0.x) + bias.x + 1.0f);
            float cand   = tanhf((s ? G1.y : G1.x) + bias.y);
            float alpha  = sigf((s ? G2.y : G2.x) + bias.z);
            float og     = sigf((s ? G3.y : G3.x) + bias.w);
            float newC;
            if (t == 0) {
                newC = cand;
            } else {
                float pC = Cprev[(size_t)r * SSZ];
                float wC = pC;
                if (t >= DIL) {
                    float dC = Ccur[(size_t)r * SSZ];  // value from t-DIL
                    wC = alpha * pC + (1.0f - alpha) * dC;
                }
                newC = forget * wC + (1.0f - forget) * cand;
            }
            Ccur[(size_t)r * SSZ] = newC;
            outv[s] = og * newC;
        }
        if (j < OSZ) {
            *reinterpret_cast<float2*>(s_out + j * 8 + 2 * p) =
                make_float2(outv[0], outv[1]);
        } else {
            Hcur[(size_t)(2 * p)     * HSZ] = outv[0];
            Hcur[(size_t)(2 * p + 1) * HSZ] = outv[1];
        }
    }
}

__global__ __launch_bounds__(NTHR, 1) void rnn_stack_kernel(
    const float* __restrict__ x,
    const float* __restrict__ b0, const float* __restrict__ b1,
    const float* __restrict__ b2, const float* __restrict__ b3,
    const float* __restrict__ Wout, const float* __restrict__ bout,
    float* __restrict__ out)
{
    __shared__ __align__(16) float s_xh[448 * 8];   // 14336 B
    __shared__ __align__(16) float s_out[1024];     //  4096 B
    __shared__ __align__(16) float s_wout[OUT_F * OSZ];

    const int tid  = threadIdx.x;
    const int row0 = blockIdx.x * RPC;

    // one-time per-step-invariant loads
    reinterpret_cast<float4*>(s_wout)[tid] =
        reinterpret_cast<const float4*>(Wout)[tid];
    float4 bs0 = make_float4(b0[tid], b0[256 + tid], b0[512 + tid], b0[768 + tid]);
    float4 bs1 = make_float4(b1[tid], b1[256 + tid], b1[512 + tid], b1[768 + tid]);
    float4 bs2 = make_float4(b2[tid], b2[256 + tid], b2[512 + tid], b2[768 + tid]);
    float4 bs3 = make_float4(b3[tid], b3[256 + tid], b3[512 + tid], b3[768 + tid]);
    const float bo = (tid < RPC * OUT_F) ? bout[tid & 7] : 0.f;

    for (int t = 0; t < T_STEPS; ++t) {
        const float4* xt4 = reinterpret_cast<const float4*>(x) +
                            ((size_t)t * BATCH + row0) * (IN_F / 4);

        do_layer<320,  1,  0, 0, 0>          (t, tid, row0, xt4, bs0, s_xh, s_out);
        do_layer<384,  3,  1, 1, 320 * 1024> (t, tid, row0, xt4, bs1, s_xh, s_out);
        do_layer<448,  6,  4, 2, 704 * 1024> (t, tid, row0, xt4, bs2, s_xh, s_out);
        do_layer<384, 12, 10, 3, 1152 * 1024>(t, tid, row0, xt4, bs3, s_xh, s_out);

        __syncthreads();  // s_out (layer-3 output) ready for projection

        if (tid < RPC * OUT_F) {
            int r = tid >> 3, o = tid & 7;
            float acc = bo;
#pragma unroll 8
            for (int q = 0; q < OSZ; ++q) {
                acc = fmaf(s_out[q * 8 + r], s_wout[o * OSZ + q], acc);
            }
            out[((size_t)t * BATCH + row0 + r) * OUT_F + o] = acc;
        }
        // next iteration's sync A protects s_out / s_xh reuse
    }
}

extern "C" void kernel_launch(void* const* d_in, const int* in_sizes, int n_in,
                              void* d_out, int out_size)
{
    (void)in_sizes; (void)n_in; (void)out_size;

    dim3 pgrid((1024 * 448 + 255) / 256, 4);
    prep_kernel<<<pgrid, 256>>>(
        (const float*)d_in[1], (const float*)d_in[3],
        (const float*)d_in[5], (const float*)d_in[7]);

    rnn_stack_kernel<<<NCTA, NTHR>>>(
        (const float*)d_in[0],
        (const float*)d_in[2], (const float*)d_in[4],
        (const float*)d_in[6], (const float*)d_in[8],
        (const float*)d_in[9], (const float*)d_in[10],
        (float*)d_out);
}

// round 4
// speedup vs baseline: 2.0123x; 1.1114x over previous
#include <cuda_runtime.h>
#include <math.h>

// ---------------------------------------------------------------------------
// DilatedSparseRnnStack — R4: 512 threads/CTA with K-split halves (4 warps per
// SMSP for latency hiding), gate-pair-packed f32x2 FMA with zero dup-MOVs
// (weights load directly as packed (g0,g1)/(g2,g3); xh staged pre-duplicated
// in SMEM). Partial accumulators reduced via SMEM scratch aliased over s_xh.
// ---------------------------------------------------------------------------

namespace {
constexpr int T_STEPS = 256;
constexpr int BATCH   = 1024;
constexpr int IN_F    = 64;
constexpr int SSZ     = 256;
constexpr int HSZ     = 128;
constexpr int OSZ     = 128;
constexpr int OUT_F   = 8;
constexpr int RPC     = 8;
constexpr int NCTA    = BATCH / RPC;   // 128
constexpr int NTHR    = 512;
constexpr int KTOT    = 320 + 384 + 448 + 384;  // 1536
}

// Transposed, gate-interleaved weights: per layer [K][1024], fast index 4*j+g.
__device__ float g_WT[(size_t)KTOT * 1024];

// Circular dilation buffers. Slot offsets {0,1,4,10}, sizes {1,3,6,12}.
__device__ float4 g_bufH4[22u * BATCH * (HSZ / 4)];
__device__ float4 g_bufC4[22u * BATCH * (SSZ / 4)];

__device__ __forceinline__ float sigf(float v) {
    return 1.0f / (1.0f + __expf(-v));
}
__device__ __forceinline__ void ffma2(unsigned long long& d,
                                      unsigned long long a,
                                      unsigned long long b) {
    asm("fma.rn.f32x2 %0, %1, %2, %0;" : "+l"(d) : "l"(a), "l"(b));
}
__device__ __forceinline__ void fadd2(unsigned long long& d,
                                      unsigned long long a) {
    asm("add.rn.f32x2 %0, %0, %1;" : "+l"(d) : "l"(a));
}
__device__ __forceinline__ float2 u2f2(unsigned long long v) {
    float2 f;
    asm("mov.b64 {%0, %1}, %2;" : "=f"(f.x), "=f"(f.y) : "l"(v));
    return f;
}

// ---------------------------------------------------------------------------
// Prep: transpose + gate-interleave weights (read-coalesced over W).
// ---------------------------------------------------------------------------
__global__ void prep_kernel(const float* __restrict__ W0,
                            const float* __restrict__ W1,
                            const float* __restrict__ W2,
                            const float* __restrict__ W3)
{
    const int li = blockIdx.y;
    const float* W;
    int K, off;
    if (li == 0)      { W = W0; K = 320; off = 0; }
    else if (li == 1) { W = W1; K = 384; off = 320 * 1024; }
    else if (li == 2) { W = W2; K = 448; off = 704 * 1024; }
    else              { W = W3; K = 384; off = 1152 * 1024; }

    int idx = blockIdx.x * 256 + threadIdx.x;
    if (idx < 1024 * K) {
        int row = idx / K;           // g*256 + j
        int k   = idx - row * K;
        int g = row >> 8, j = row & 255;
        g_WT[(size_t)off + (size_t)k * 1024 + 4 * j + g] = W[idx];
    }
}

// ---------------------------------------------------------------------------
// One layer step. 512 threads: half = tid>>8 processes k in [half*K/2, ...).
// s_big: 32KB scratch. During GEMM it holds xh dup-pairs (float2 {v,v} at
// index k*8+r, 28KB). After GEMM it is reused as the reduction buffer.
// ---------------------------------------------------------------------------
template <int K, int DIL, int LOFF, int LI, int WTOFF>
__device__ __forceinline__ void do_layer(
    int t, int tid, int row0,
    const float4* __restrict__ xt4,
    float4 bias,
    unsigned long long* __restrict__ s_big,
    float* __restrict__ s_out)   // [128 j][8 r]
{
    const int prevSlot = LOFF + (t - 1 + DIL) % DIL;
    const int curSlot  = LOFF + (t % DIL);
    const int half = tid >> 8;
    const int j    = tid & 255;

    float2* s_xh2 = reinterpret_cast<float2*>(s_big);

    __syncthreads();  // sync A: prev layer fully consumed (incl. reduction reads)

    // ---- build xh dup-pairs in SMEM: s_xh2[k*8 + r] = {v, v} ----
    if (LI > 0) {
        // out section at k-offset 0: s_out[j*8+r] -> identity index mapping
        float v0 = s_out[tid];
        float v1 = s_out[tid + 512];
        s_xh2[tid]       = make_float2(v0, v0);
        s_xh2[tid + 512] = make_float2(v1, v1);
    }
    if (LI == 0 || LI == 2) {
        constexpr int XOFF = (LI == 0) ? 0 : OSZ;
        if (tid < 128) {
            int r = tid & 7, k4 = tid >> 3;
            float4 v = xt4[r * (IN_F / 4) + k4];
            int b = (XOFF + 4 * k4) * 8 + r;
            s_xh2[b]      = make_float2(v.x, v.x);
            s_xh2[b + 8]  = make_float2(v.y, v.y);
            s_xh2[b + 16] = make_float2(v.z, v.z);
            s_xh2[b + 24] = make_float2(v.w, v.w);
        }
    }
    {
        constexpr int HOFF = (LI == 0) ? IN_F : (LI == 2) ? (OSZ + IN_F) : OSZ;
        int it = tid & 255;
        int r = it & 7, c = it >> 3;                 // c in 0..31
        if (half == 0) {
            float4 pv = (t > 0)
                ? g_bufH4[((size_t)prevSlot * BATCH + row0 + r) * (HSZ / 4) + c]
                : make_float4(0.f, 0.f, 0.f, 0.f);
            int b = (HOFF + 4 * c) * 8 + r;
            s_xh2[b]      = make_float2(pv.x, pv.x);
            s_xh2[b + 8]  = make_float2(pv.y, pv.y);
            s_xh2[b + 16] = make_float2(pv.z, pv.z);
            s_xh2[b + 24] = make_float2(pv.w, pv.w);
        } else {
            float4 dv;
            if (t >= DIL) {
                dv = g_bufH4[((size_t)curSlot * BATCH + row0 + r) * (HSZ / 4) + c];
            } else if (t > 0) {
                dv = g_bufH4[((size_t)prevSlot * BATCH + row0 + r) * (HSZ / 4) + c];
            } else {
                dv = make_float4(0.f, 0.f, 0.f, 0.f);
            }
            int b = (HOFF + HSZ + 4 * c) * 8 + r;
            s_xh2[b]      = make_float2(dv.x, dv.x);
            s_xh2[b + 8]  = make_float2(dv.y, dv.y);
            s_xh2[b + 16] = make_float2(dv.z, dv.z);
            s_xh2[b + 24] = make_float2(dv.w, dv.w);
        }
    }

    __syncthreads();  // sync B: xh complete

    // ---- GEMM over this half's k-range ----
    const ulonglong2* __restrict__ wt2 =
        reinterpret_cast<const ulonglong2*>(g_WT + WTOFF) + j;
    const ulonglong2* __restrict__ sx =
        reinterpret_cast<const ulonglong2*>(s_big);
    const int k0 = half * (K / 2);

    unsigned long long a01[8], a23[8];
#pragma unroll
    for (int r = 0; r < 8; ++r) { a01[r] = 0ull; a23[r] = 0ull; }

#pragma unroll 2
    for (int kk = 0; kk < K / 2; ++kk) {
        const int k = k0 + kk;
        ulonglong2 wp = wt2[(size_t)k * 256];        // {(g0,g1),(g2,g3)}
        ulonglong2 xA = sx[k * 4 + 0];               // rows 0,1 dup-pairs
        ulonglong2 xB = sx[k * 4 + 1];               // rows 2,3
        ulonglong2 xC = sx[k * 4 + 2];               // rows 4,5
        ulonglong2 xD = sx[k * 4 + 3];               // rows 6,7
        ffma2(a01[0], wp.x, xA.x); ffma2(a23[0], wp.y, xA.x);
        ffma2(a01[1], wp.x, xA.y); ffma2(a23[1], wp.y, xA.y);
        ffma2(a01[2], wp.x, xB.x); ffma2(a23[2], wp.y, xB.x);
        ffma2(a01[3], wp.x, xB.y); ffma2(a23[3], wp.y, xB.y);
        ffma2(a01[4], wp.x, xC.x); ffma2(a23[4], wp.y, xC.x);
        ffma2(a01[5], wp.x, xC.y); ffma2(a23[5], wp.y, xC.y);
        ffma2(a01[6], wp.x, xD.x); ffma2(a23[6], wp.y, xD.x);
        ffma2(a01[7], wp.x, xD.y); ffma2(a23[7], wp.y, xD.y);
    }

    __syncthreads();  // sync C: xh reads done; s_big reusable as reduction buf

    if (half == 1) {
#pragma unroll
        for (int r = 0; r < 8; ++r) {
            s_big[r * 256 + j]         = a01[r];
            s_big[(8 + r) * 256 + j]   = a23[r];
        }
    }

    __syncthreads();  // sync D: partials visible

    if (half == 0) {
#pragma unroll
        for (int r = 0; r < 8; ++r) {
            fadd2(a01[r], s_big[r * 256 + j]);
            fadd2(a23[r], s_big[(8 + r) * 256 + j]);
        }

        // ---- epilogue ----
        float* Cbase = reinterpret_cast<float*>(g_bufC4);
        float* Hbase = reinterpret_cast<float*>(g_bufH4);
        float*       Ccur  = Cbase + ((size_t)curSlot  * BATCH + row0) * SSZ + j;
        const float* Cprev = Cbase + ((size_t)prevSlot * BATCH + row0) * SSZ + j;
        float*       Hcur  = Hbase + ((size_t)curSlot  * BATCH + row0) * HSZ + (j - OSZ);

#pragma unroll
        for (int r = 0; r < 8; ++r) {
            float2 G01 = u2f2(a01[r]);
            float2 G23 = u2f2(a23[r]);
            float forget = sigf(G01.x + bias.x + 1.0f);
            float cand   = tanhf(G01.y + bias.y);
            float alpha  = sigf(G23.x + bias.z);
            float og     = sigf(G23.y + bias.w);
            float newC;
            if (t == 0) {
                newC = cand;
            } else {
                float pC = Cprev[(size_t)r * SSZ];
                float wC = pC;
                if (t >= DIL) {
                    float dC = Ccur[(size_t)r * SSZ];   // value from t-DIL
                    wC = alpha * pC + (1.0f - alpha) * dC;
                }
                newC = forget * wC + (1.0f - forget) * cand;
            }
            Ccur[(size_t)r * SSZ] = newC;
            float whole = og * newC;
            if (j < OSZ) {
                s_out[j * 8 + r] = whole;
            } else {
                Hcur[(size_t)r * HSZ] = whole;
            }
        }
    }
}

__global__ __launch_bounds__(NTHR, 1) void rnn_stack_kernel(
    const float* __restrict__ x,
    const float* __restrict__ b0, const float* __restrict__ b1,
    const float* __restrict__ b2, const float* __restrict__ b3,
    const float* __restrict__ Wout, const float* __restrict__ bout,
    float* __restrict__ out)
{
    __shared__ __align__(16) unsigned long long s_big[4096];  // 32 KB
    __shared__ __align__(16) float s_out[1024];               //  4 KB
    __shared__ __align__(16) float s_wout[OUT_F * OSZ];       //  4 KB

    const int tid  = threadIdx.x;
    const int row0 = blockIdx.x * RPC;
    const int j    = tid & 255;

    if (tid < 256) {
        reinterpret_cast<float4*>(s_wout)[tid] =
            reinterpret_cast<const float4*>(Wout)[tid];
    }
    float4 bs0 = make_float4(b0[j], b0[256 + j], b0[512 + j], b0[768 + j]);
    float4 bs1 = make_float4(b1[j], b1[256 + j], b1[512 + j], b1[768 + j]);
    float4 bs2 = make_float4(b2[j], b2[256 + j], b2[512 + j], b2[768 + j]);
    float4 bs3 = make_float4(b3[j], b3[256 + j], b3[512 + j], b3[768 + j]);
    const float bo = (tid < RPC * OUT_F) ? bout[tid & 7] : 0.f;

    for (int t = 0; t < T_STEPS; ++t) {
        const float4* xt4 = reinterpret_cast<const float4*>(x) +
                            ((size_t)t * BATCH + row0) * (IN_F / 4);

        do_layer<320,  1,  0, 0, 0>          (t, tid, row0, xt4, bs0, s_big, s_out);
        do_layer<384,  3,  1, 1, 320 * 1024> (t, tid, row0, xt4, bs1, s_big, s_out);
        do_layer<448,  6,  4, 2, 704 * 1024> (t, tid, row0, xt4, bs2, s_big, s_out);
        do_layer<384, 12, 10, 3, 1152 * 1024>(t, tid, row0, xt4, bs3, s_big, s_out);

        __syncthreads();  // layer-3 s_out ready

        if (tid < RPC * OUT_F) {
            int r = tid >> 3, o = tid & 7;
            float acc = bo;
#pragma unroll 8
            for (int q = 0; q < OSZ; ++q) {
                acc = fmaf(s_out[q * 8 + r], s_wout[o * OSZ + q], acc);
            }
            out[((size_t)t * BATCH + row0 + r) * OUT_F + o] = acc;
        }
        // next iteration's sync A protects s_out / s_big reuse
    }
}

extern "C" void kernel_launch(void* const* d_in, const int* in_sizes, int n_in,
                              void* d_out, int out_size)
{
    (void)in_sizes; (void)n_in; (void)out_size;

    dim3 pgrid((1024 * 448 + 255) / 256, 4);
    prep_kernel<<<pgrid, 256>>>(
        (const float*)d_in[1], (const float*)d_in[3],
        (const float*)d_in[5], (const float*)d_in[7]);

    rnn_stack_kernel<<<NCTA, NTHR>>>(
        (const float*)d_in[0],
        (const float*)d_in[2], (const float*)d_in[4],
        (const float*)d_in[6], (const float*)d_in[8],
        (const float*)d_in[9], (const float*)d_in[10],
        (float*)d_out);
}

// round 5
// speedup vs baseline: 2.4556x; 1.2203x over previous
#include <cuda_runtime.h>
#include <math.h>

// ---------------------------------------------------------------------------
// DilatedSparseRnnStack — R5: pointer-walked unrolled GEMM (kills ALU address
// math), balanced split reduction+epilogue (half0 owns rows 0-3, half1 rows
// 4-7), C-state prefetch under the GEMM, full-width output projection.
// ---------------------------------------------------------------------------

namespace {
constexpr int T_STEPS = 256;
constexpr int BATCH   = 1024;
constexpr int IN_F    = 64;
constexpr int SSZ     = 256;
constexpr int HSZ     = 128;
constexpr int OSZ     = 128;
constexpr int OUT_F   = 8;
constexpr int RPC     = 8;
constexpr int NCTA    = BATCH / RPC;   // 128
constexpr int NTHR    = 512;
constexpr int KTOT    = 320 + 384 + 448 + 384;  // 1536
}

// Transposed, gate-interleaved weights: per layer [K][1024], fast index 4*j+g.
__device__ float g_WT[(size_t)KTOT * 1024];

// Circular dilation buffers. Slot offsets {0,1,4,10}, sizes {1,3,6,12}.
__device__ float4 g_bufH4[22u * BATCH * (HSZ / 4)];
__device__ float4 g_bufC4[22u * BATCH * (SSZ / 4)];

__device__ __forceinline__ float sigf(float v) {
    return 1.0f / (1.0f + __expf(-v));
}
__device__ __forceinline__ void ffma2(unsigned long long& d,
                                      unsigned long long a,
                                      unsigned long long b) {
    asm("fma.rn.f32x2 %0, %1, %2, %0;" : "+l"(d) : "l"(a), "l"(b));
}
__device__ __forceinline__ void fadd2(unsigned long long& d,
                                      unsigned long long a) {
    asm("add.rn.f32x2 %0, %0, %1;" : "+l"(d) : "l"(a));
}
__device__ __forceinline__ float2 u2f2(unsigned long long v) {
    float2 f;
    asm("mov.b64 {%0, %1}, %2;" : "=f"(f.x), "=f"(f.y) : "l"(v));
    return f;
}

// ---------------------------------------------------------------------------
// Prep: transpose + gate-interleave weights (read-coalesced over W).
// ---------------------------------------------------------------------------
__global__ void prep_kernel(const float* __restrict__ W0,
                            const float* __restrict__ W1,
                            const float* __restrict__ W2,
                            const float* __restrict__ W3)
{
    const int li = blockIdx.y;
    const float* W;
    int K, off;
    if (li == 0)      { W = W0; K = 320; off = 0; }
    else if (li == 1) { W = W1; K = 384; off = 320 * 1024; }
    else if (li == 2) { W = W2; K = 448; off = 704 * 1024; }
    else              { W = W3; K = 384; off = 1152 * 1024; }

    int idx = blockIdx.x * 256 + threadIdx.x;
    if (idx < 1024 * K) {
        int row = idx / K;           // g*256 + j
        int k   = idx - row * K;
        int g = row >> 8, j = row & 255;
        g_WT[(size_t)off + (size_t)k * 1024 + 4 * j + g] = W[idx];
    }
}

// ---------------------------------------------------------------------------
// One layer step. 512 threads: half = tid>>8 handles k-range half.
// Epilogue rows: half0 -> rows 0-3, half1 -> rows 4-7 (balanced).
// s_big: 32KB scratch: xh dup-pairs during GEMM, then reduction buffer.
// ---------------------------------------------------------------------------
template <int K, int DIL, int LOFF, int LI, int WTOFF>
__device__ __forceinline__ void do_layer(
    int t, int tid, int row0,
    const float4* __restrict__ xt4,
    float4 bias,
    unsigned long long* __restrict__ s_big,
    float* __restrict__ s_out)   // [128 j][8 r]
{
    const int prevSlot = LOFF + (t - 1 + DIL) % DIL;
    const int curSlot  = LOFF + (t % DIL);
    const int half = tid >> 8;
    const int j    = tid & 255;
    const int rb   = half * 4;           // rows this thread epilogues

    float2* s_xh2 = reinterpret_cast<float2*>(s_big);

    __syncthreads();  // sync A: prev layer fully consumed

    // ---- C-state prefetch (consumed in epilogue; hides L2 latency) ----
    float* Cbase = reinterpret_cast<float*>(g_bufC4);
    float*       Ccur  = Cbase + ((size_t)curSlot  * BATCH + row0) * SSZ + j;
    const float* Cprev = Cbase + ((size_t)prevSlot * BATCH + row0) * SSZ + j;
    float pC[4]  = {0.f, 0.f, 0.f, 0.f};
    float dCv[4] = {0.f, 0.f, 0.f, 0.f};
    if (t > 0) {
#pragma unroll
        for (int r = 0; r < 4; ++r) pC[r] = Cprev[(size_t)(rb + r) * SSZ];
    }
    if (t >= DIL) {
#pragma unroll
        for (int r = 0; r < 4; ++r) dCv[r] = Ccur[(size_t)(rb + r) * SSZ];
    }

    // ---- build xh dup-pairs in SMEM: s_xh2[k*8 + r] = {v, v} ----
    if (LI > 0) {
        float v0 = s_out[tid];
        float v1 = s_out[tid + 512];
        s_xh2[tid]       = make_float2(v0, v0);
        s_xh2[tid + 512] = make_float2(v1, v1);
    }
    if (LI == 0 || LI == 2) {
        constexpr int XOFF = (LI == 0) ? 0 : OSZ;
        if (tid < 128) {
            int r = tid & 7, k4 = tid >> 3;
            float4 v = xt4[r * (IN_F / 4) + k4];
            int b = (XOFF + 4 * k4) * 8 + r;
            s_xh2[b]      = make_float2(v.x, v.x);
            s_xh2[b + 8]  = make_float2(v.y, v.y);
            s_xh2[b + 16] = make_float2(v.z, v.z);
            s_xh2[b + 24] = make_float2(v.w, v.w);
        }
    }
    {
        constexpr int HOFF = (LI == 0) ? IN_F : (LI == 2) ? (OSZ + IN_F) : OSZ;
        int r = j & 7, c = j >> 3;                 // c in 0..31
        if (half == 0) {
            float4 pv = (t > 0)
                ? g_bufH4[((size_t)prevSlot * BATCH + row0 + r) * (HSZ / 4) + c]
                : make_float4(0.f, 0.f, 0.f, 0.f);
            int b = (HOFF + 4 * c) * 8 + r;
            s_xh2[b]      = make_float2(pv.x, pv.x);
            s_xh2[b + 8]  = make_float2(pv.y, pv.y);
            s_xh2[b + 16] = make_float2(pv.z, pv.z);
            s_xh2[b + 24] = make_float2(pv.w, pv.w);
        } else {
            float4 dv;
            if (t >= DIL) {
                dv = g_bufH4[((size_t)curSlot * BATCH + row0 + r) * (HSZ / 4) + c];
            } else if (t > 0) {
                dv = g_bufH4[((size_t)prevSlot * BATCH + row0 + r) * (HSZ / 4) + c];
            } else {
                dv = make_float4(0.f, 0.f, 0.f, 0.f);
            }
            int b = (HOFF + HSZ + 4 * c) * 8 + r;
            s_xh2[b]      = make_float2(dv.x, dv.x);
            s_xh2[b + 8]  = make_float2(dv.y, dv.y);
            s_xh2[b + 16] = make_float2(dv.z, dv.z);
            s_xh2[b + 24] = make_float2(dv.w, dv.w);
        }
    }

    __syncthreads();  // sync B: xh complete

    // ---- GEMM over this half's k-range (pointer-walked, unroll 8) ----
    unsigned long long a01[8], a23[8];
#pragma unroll
    for (int r = 0; r < 8; ++r) { a01[r] = 0ull; a23[r] = 0ull; }

    {
        const char* wp = reinterpret_cast<const char*>(g_WT + WTOFF)
                       + (size_t)j * 16 + (size_t)half * (K / 2) * 4096;
        const char* xp = reinterpret_cast<const char*>(s_big)
                       + half * (K / 2) * 64;
        for (int kb = 0; kb < K / 2; kb += 8) {
#pragma unroll
            for (int u = 0; u < 8; ++u) {
                ulonglong2 w  = *reinterpret_cast<const ulonglong2*>(wp + u * 4096);
                ulonglong2 xA = *reinterpret_cast<const ulonglong2*>(xp + u * 64);
                ulonglong2 xB = *reinterpret_cast<const ulonglong2*>(xp + u * 64 + 16);
                ulonglong2 xC = *reinterpret_cast<const ulonglong2*>(xp + u * 64 + 32);
                ulonglong2 xD = *reinterpret_cast<const ulonglong2*>(xp + u * 64 + 48);
                ffma2(a01[0], w.x, xA.x); ffma2(a23[0], w.y, xA.x);
                ffma2(a01[1], w.x, xA.y); ffma2(a23[1], w.y, xA.y);
                ffma2(a01[2], w.x, xB.x); ffma2(a23[2], w.y, xB.x);
                ffma2(a01[3], w.x, xB.y); ffma2(a23[3], w.y, xB.y);
                ffma2(a01[4], w.x, xC.x); ffma2(a23[4], w.y, xC.x);
                ffma2(a01[5], w.x, xC.y); ffma2(a23[5], w.y, xC.y);
                ffma2(a01[6], w.x, xD.x); ffma2(a23[6], w.y, xD.x);
                ffma2(a01[7], w.x, xD.y); ffma2(a23[7], w.y, xD.y);
            }
            wp += 8 * 4096;
            xp += 8 * 64;
        }
    }

    __syncthreads();  // sync C: xh reads done; s_big becomes reduction buffer

    // ---- balanced reduction: write partials for NON-owned rows ----
    {
        const int other = rb ^ 4;
        const int wbase = half * 2048;
#pragma unroll
        for (int i = 0; i < 4; ++i) {
            s_big[wbase + i * 256 + j]       = a01[other + i];
            s_big[wbase + (4 + i) * 256 + j] = a23[other + i];
        }
    }

    __syncthreads();  // sync D: partials visible

    {
        const int rbase2 = 2048 - half * 2048;
#pragma unroll
        for (int i = 0; i < 4; ++i) {
            fadd2(a01[rb + i], s_big[rbase2 + i * 256 + j]);
            fadd2(a23[rb + i], s_big[rbase2 + (4 + i) * 256 + j]);
        }
    }

    // ---- epilogue: 4 rows per thread, both halves in parallel ----
    float* Hbase = reinterpret_cast<float*>(g_bufH4);
    float* Hcur  = Hbase + ((size_t)curSlot * BATCH + row0) * HSZ + (j - OSZ);

    float whole[4];
#pragma unroll
    for (int r = 0; r < 4; ++r) {
        const int row = rb + r;
        float2 G01 = u2f2(a01[row]);
        float2 G23 = u2f2(a23[row]);
        float forget = sigf(G01.x + bias.x + 1.0f);
        float cand   = tanhf(G01.y + bias.y);
        float alpha  = sigf(G23.x + bias.z);
        float og     = sigf(G23.y + bias.w);
        float newC;
        if (t == 0) {
            newC = cand;
        } else {
            float wC = pC[r];
            if (t >= DIL) {
                wC = alpha * pC[r] + (1.0f - alpha) * dCv[r];
            }
            newC = forget * wC + (1.0f - forget) * cand;
        }
        Ccur[(size_t)row * SSZ] = newC;
        whole[r] = og * newC;
    }
    if (j < OSZ) {
        reinterpret_cast<float4*>(s_out)[j * 2 + half] =
            make_float4(whole[0], whole[1], whole[2], whole[3]);
    } else {
#pragma unroll
        for (int r = 0; r < 4; ++r) {
            Hcur[(size_t)(rb + r) * HSZ] = whole[r];
        }
    }
}

__global__ __launch_bounds__(NTHR, 1) void rnn_stack_kernel(
    const float* __restrict__ x,
    const float* __restrict__ b0, const float* __restrict__ b1,
    const float* __restrict__ b2, const float* __restrict__ b3,
    const float* __restrict__ Wout, const float* __restrict__ bout,
    float* __restrict__ out)
{
    __shared__ __align__(16) unsigned long long s_big[4096];  // 32 KB
    __shared__ __align__(16) float s_out[1024];               //  4 KB
    __shared__ __align__(16) float s_wout[OUT_F * OSZ];       //  4 KB

    const int tid  = threadIdx.x;
    const int row0 = blockIdx.x * RPC;
    const int j    = tid & 255;

    if (tid < 256) {
        reinterpret_cast<float4*>(s_wout)[tid] =
            reinterpret_cast<const float4*>(Wout)[tid];
    }
    float4 bs0 = make_float4(b0[j], b0[256 + j], b0[512 + j], b0[768 + j]);
    float4 bs1 = make_float4(b1[j], b1[256 + j], b1[512 + j], b1[768 + j]);
    float4 bs2 = make_float4(b2[j], b2[256 + j], b2[512 + j], b2[768 + j]);
    float4 bs3 = make_float4(b3[j], b3[256 + j], b3[512 + j], b3[768 + j]);

    // projection mapping: seg = tid&7 (k-segment), o = (tid>>3)&7, r = tid>>6
    const int p_seg = tid & 7;
    const int p_o   = (tid >> 3) & 7;
    const int p_r   = tid >> 6;
    const float bo  = bout[p_o];

    for (int t = 0; t < T_STEPS; ++t) {
        const float4* xt4 = reinterpret_cast<const float4*>(x) +
                            ((size_t)t * BATCH + row0) * (IN_F / 4);

        do_layer<320,  1,  0, 0, 0>          (t, tid, row0, xt4, bs0, s_big, s_out);
        do_layer<384,  3,  1, 1, 320 * 1024> (t, tid, row0, xt4, bs1, s_big, s_out);
        do_layer<448,  6,  4, 2, 704 * 1024> (t, tid, row0, xt4, bs2, s_big, s_out);
        do_layer<384, 12, 10, 3, 1152 * 1024>(t, tid, row0, xt4, bs3, s_big, s_out);

        __syncthreads();  // layer-3 s_out ready

        // ---- output projection: all 512 threads, shfl octet reduction ----
        {
            float acc = 0.f;
#pragma unroll
            for (int qq = 0; qq < 16; ++qq) {
                int q = qq * 8 + p_seg;
                acc = fmaf(s_out[q * 8 + p_r], s_wout[p_o * OSZ + q], acc);
            }
            acc += __shfl_down_sync(0xffffffffu, acc, 4);
            acc += __shfl_down_sync(0xffffffffu, acc, 2);
            acc += __shfl_down_sync(0xffffffffu, acc, 1);
            if (p_seg == 0) {
                out[((size_t)t * BATCH + row0 + p_r) * OUT_F + p_o] = acc + bo;
            }
        }
        // next iteration's sync A protects s_out / s_big reuse
    }
}

extern "C" void kernel_launch(void* const* d_in, const int* in_sizes, int n_in,
                              void* d_out, int out_size)
{
    (void)in_sizes; (void)n_in; (void)out_size;

    dim3 pgrid((1024 * 448 + 255) / 256, 4);
    prep_kernel<<<pgrid, 256>>>(
        (const float*)d_in[1], (const float*)d_in[3],
        (const float*)d_in[5], (const float*)d_in[7]);

    rnn_stack_kernel<<<NCTA, NTHR>>>(
        (const float*)d_in[0],
        (const float*)d_in[2], (const float*)d_in[4],
        (const float*)d_in[6], (const float*)d_in[8],
        (const float*)d_in[9], (const float*)d_in[10],
        (float*)d_out);
}